// round 2
// baseline (speedup 1.0000x reference)
#include <cuda_runtime.h>

#define BB 4
#define CC 64
#define HH 192
#define WWI 192
#define HWSZ (HH*WWI)
#define HD 96
#define WD 96

// ---- scratch (static device globals; no runtime allocation) ----
__device__ float g_down[BB*CC*HD*WD];          // 9.4 MB
__device__ float g_df[BB*HWSZ];
__device__ float g_nsq[BB*HWSZ];
__device__ unsigned g_dfmin[BB];
__device__ unsigned g_dfmax[BB];
__device__ float g_sum[BB*CC];
__device__ float g_ssq[BB*CC];
__device__ float g_A[BB*CC];
__device__ float g_Bc[BB*CC];
__device__ float g_enh[(size_t)BB*CC*HWSZ];    // 37.7 MB

__global__ void k_init() {
    int t = threadIdx.x;
    if (t < BB) { g_dfmin[t] = 0x7f800000u; g_dfmax[t] = 0u; }
}

// 0.5x bilinear == 2x2 average pooling (half-pixel centers, w=0.5 exactly)
__global__ void k_down(const float* __restrict__ x) {
    int i = blockIdx.x * 256 + threadIdx.x;
    if (i >= BB*CC*HD*WD) return;
    int j  = i % WD;
    int t  = i / WD;
    int ii = t % HD;
    int bc = t / HD;
    const float* xp = x + (size_t)bc * HWSZ + (2*ii) * WWI + 2*j;
    float a = xp[0], b = xp[1], c = xp[WWI], d = xp[WWI+1];
    float r0 = 0.5f*a + 0.5f*c;   // resize H first (matches reference order)
    float r1 = 0.5f*b + 0.5f*d;
    g_down[i] = 0.5f*r0 + 0.5f*r1;
}

// df map (sum_c |x - up(down(x))|), per-pixel normsq over C, per-batch min/max
__global__ void k_df(const float* __restrict__ x) {
    int p = blockIdx.x * 256 + threadIdx.x;   // 0..HWSZ-1 (exact)
    int b = blockIdx.y;
    int h = p / WWI, w = p % WWI;

    float sh = fminf(fmaxf((h + 0.5f) * 0.5f - 0.5f, 0.f), (float)(HD-1));
    float sw = fminf(fmaxf((w + 0.5f) * 0.5f - 0.5f, 0.f), (float)(WD-1));
    int hl = (int)sh; int hh2 = min(hl+1, HD-1); float wh = sh - (float)hl;
    int wl = (int)sw; int wh2 = min(wl+1, WD-1); float ww = sw - (float)wl;
    int i00 = hl*WD+wl, i10 = hh2*WD+wl, i01 = hl*WD+wh2, i11 = hh2*WD+wh2;

    const float* xb = x + (size_t)b * CC * HWSZ + p;
    const float* db = g_down + (size_t)b * CC * HD * WD;

    float df = 0.f, nsq = 0.f;
    #pragma unroll 4
    for (int c = 0; c < CC; c++) {
        float xv = xb[(size_t)c * HWSZ];
        const float* dc = db + c * HD * WD;
        float u0  = dc[i00]*(1.f-wh) + dc[i10]*wh;   // H interp
        float u1  = dc[i01]*(1.f-wh) + dc[i11]*wh;
        float xdu = u0*(1.f-ww) + u1*ww;             // then W interp
        df  += fabsf(xv - xdu);
        nsq += xv * xv;
    }
    g_df[b*HWSZ+p]  = df;
    g_nsq[b*HWSZ+p] = nsq;

    __shared__ float smn[256], smx[256];
    int tid = threadIdx.x;
    smn[tid] = df; smx[tid] = df;
    __syncthreads();
    for (int s = 128; s > 0; s >>= 1) {
        if (tid < s) {
            smn[tid] = fminf(smn[tid], smn[tid+s]);
            smx[tid] = fmaxf(smx[tid], smx[tid+s]);
        }
        __syncthreads();
    }
    if (tid == 0) {
        atomicMin(&g_dfmin[b], __float_as_uint(smn[0]));   // df >= 0: uint order == float order
        atomicMax(&g_dfmax[b], __float_as_uint(smx[0]));
    }
}

// per-(b,c) sum / sumsq for GroupNorm
__global__ void k_gnstats(const float* __restrict__ x) {
    int bc = blockIdx.x;   // 0..BB*CC-1
    const float* xp = x + (size_t)bc * HWSZ;
    float s = 0.f, q = 0.f;
    for (int i = threadIdx.x; i < HWSZ; i += 256) {
        float v = xp[i];
        s += v; q += v*v;
    }
    __shared__ float ss[256], sq[256];
    ss[threadIdx.x] = s; sq[threadIdx.x] = q;
    __syncthreads();
    for (int st = 128; st > 0; st >>= 1) {
        if (threadIdx.x < st) {
            ss[threadIdx.x] += ss[threadIdx.x+st];
            sq[threadIdx.x] += sq[threadIdx.x+st];
        }
        __syncthreads();
    }
    if (threadIdx.x == 0) { g_sum[bc] = ss[0]; g_ssq[bc] = sq[0]; }
}

// fold GN(32 groups of 2 channels) into per-(b,c) affine A*x + B
__global__ void k_gnfin(const float* __restrict__ gw, const float* __restrict__ gb) {
    int t = threadIdx.x;              // 256 = BB*CC
    int c = t % CC;
    int g = c >> 1;
    int base = (t / CC) * CC + 2 * g;
    float n   = 2.f * (float)HWSZ;
    float mu  = (g_sum[base] + g_sum[base+1]) / n;
    float var = (g_ssq[base] + g_ssq[base+1]) / n - mu*mu;
    float inv = rsqrtf(var + 1e-5f);
    float A = gw[c] * inv;
    g_A[t]  = A;
    g_Bc[t] = gb[c] - mu * A;
}

// main fused kernel: detail gating + cosine top-k aggregation + GN add -> enhanced
__global__ void k_main(const float* __restrict__ x) {
    int p = blockIdx.x * 256 + threadIdx.x;
    int b = blockIdx.y;

    __shared__ float sA[CC], sB[CC];
    if (threadIdx.x < CC) {
        sA[threadIdx.x] = g_A [b*CC + threadIdx.x];
        sB[threadIdx.x] = g_Bc[b*CC + threadIdx.x];
    }
    __syncthreads();

    int h = p / WWI, w = p % WWI;
    const float* xb = x + (size_t)b * CC * HWSZ + p;
    float* eb = g_enh + (size_t)b * CC * HWSZ + p;

    float dmin = __uint_as_float(g_dfmin[b]);
    float dmax = __uint_as_float(g_dfmax[b]);
    float df   = g_df[b*HWSZ + p];
    float t0   = (df - dmin) / ((dmax - dmin) + 1e-8f);
    float dfp  = t0 * t0;

    if (!(dfp > 0.3f)) {   // mask==0 -> conn==1 -> not processed: enhanced = x + (A*x+B)
        #pragma unroll 8
        for (int c = 0; c < CC; c++) {
            float xv = xb[(size_t)c * HWSZ];
            eb[(size_t)c * HWSZ] = xv + (sA[c]*xv + sB[c]);
        }
        return;
    }

    int kk = min(1 + (int)rintf(dfp * 15.f), 9);

    bool val[9];
    int  doff[9];
    #pragma unroll
    for (int j = 0; j < 9; j++) {
        int dy = j/3 - 1, dx = j - 3*(j/3) - 1;
        val[j]  = ((unsigned)(h+dy) < HH) && ((unsigned)(w+dx) < WWI);
        doff[j] = dy * WWI + dx;
    }

    float dot[9];
    #pragma unroll
    for (int j = 0; j < 9; j++) dot[j] = 0.f;

    #pragma unroll 4
    for (int c = 0; c < CC; c++) {
        const float* rc = xb + (size_t)c * HWSZ;
        float xv = rc[0];
        #pragma unroll
        for (int j = 0; j < 9; j++)
            if (val[j]) dot[j] = fmaf(xv, rc[doff[j]], dot[j]);
    }

    float ncen = fmaxf(sqrtf(g_nsq[b*HWSZ + p]), 1e-12f);
    float sim[9];
    #pragma unroll
    for (int j = 0; j < 9; j++) {
        if (val[j]) {
            float nn = fmaxf(sqrtf(g_nsq[b*HWSZ + p + doff[j]]), 1e-12f);
            sim[j] = dot[j] / (ncen * nn);
        } else {
            sim[j] = 0.f;   // zero-padded patch: pn = 0 -> sim = 0
        }
    }

    // stable top-k via rank (== stable argsort of -sim), all in registers
    float wt[9];
    float wsum = 0.f;
    #pragma unroll
    for (int j = 0; j < 9; j++) {
        int rank = 0;
        #pragma unroll
        for (int l = 0; l < 9; l++) {
            if (l != j) {
                bool beats = (sim[l] > sim[j]) || (sim[l] == sim[j] && l < j);
                rank += beats ? 1 : 0;
            }
        }
        float wv = (rank < kk) ? expf(sim[j]) : 0.f;
        wt[j] = wv;
        wsum += wv;
    }
    float invw = 1.f / fmaxf(wsum, 1e-12f);
    #pragma unroll
    for (int j = 0; j < 9; j++) wt[j] *= invw;

    #pragma unroll 4
    for (int c = 0; c < CC; c++) {
        const float* rc = xb + (size_t)c * HWSZ;
        float acc = 0.f;
        #pragma unroll
        for (int j = 0; j < 9; j++)
            if (val[j]) acc = fmaf(wt[j], rc[doff[j]], acc);
        float xv = rc[0];
        eb[(size_t)c * HWSZ] = acc + (sA[c]*xv + sB[c]);
    }
}

// FFN: out = enhanced + (W2 @ relu(W1 @ enhanced + b1) + b2); both W in smem
__global__ void __launch_bounds__(128) k_ffn(
    const float* __restrict__ w1, const float* __restrict__ b1,
    const float* __restrict__ w2, const float* __restrict__ b2,
    float* __restrict__ out)
{
    extern __shared__ float sm[];
    float* sW1  = sm;           // [128][64] row-major
    float* sW2t = sm + 8192;    // [o][c] = w2[c][o] (transposed for LDS.128 over c)
    float* sb1  = sm + 16384;   // [128]
    float* sb2  = sm + 16512;   // [64]
    int tid = threadIdx.x;
    for (int i = tid; i < 8192; i += 128) sW1[i] = w1[i];
    for (int i = tid; i < 8192; i += 128) {
        int o = i >> 6, c = i & 63;
        sW2t[i] = w2[c * 128 + o];
    }
    sb1[tid] = b1[tid];
    if (tid < 64) sb2[tid] = b2[tid];
    __syncthreads();

    int n = blockIdx.x * 128 + tid;     // 0..BB*HWSZ-1 (exact)
    int b = n / HWSZ;
    int p = n - b * HWSZ;
    const float* E = g_enh + (size_t)b * CC * HWSZ + p;

    float e[64], acc[64];
    #pragma unroll
    for (int c = 0; c < 64; c++) e[c] = E[(size_t)c * HWSZ];
    #pragma unroll
    for (int c = 0; c < 64; c++) acc[c] = e[c] + sb2[c];   // enhanced + b2

    #pragma unroll 2
    for (int o = 0; o < 128; o++) {
        const float4* wr = (const float4*)(sW1 + o * 64);
        float h0 = 0.f, h1 = 0.f, h2 = 0.f, h3 = 0.f;
        #pragma unroll
        for (int q = 0; q < 16; q++) {
            float4 v = wr[q];
            h0 = fmaf(v.x, e[4*q+0], h0);
            h1 = fmaf(v.y, e[4*q+1], h1);
            h2 = fmaf(v.z, e[4*q+2], h2);
            h3 = fmaf(v.w, e[4*q+3], h3);
        }
        float hh = fmaxf((h0 + h1) + (h2 + h3) + sb1[o], 0.f);
        const float4* wc = (const float4*)(sW2t + o * 64);
        #pragma unroll
        for (int q = 0; q < 16; q++) {
            float4 v = wc[q];
            acc[4*q+0] = fmaf(v.x, hh, acc[4*q+0]);
            acc[4*q+1] = fmaf(v.y, hh, acc[4*q+1]);
            acc[4*q+2] = fmaf(v.z, hh, acc[4*q+2]);
            acc[4*q+3] = fmaf(v.w, hh, acc[4*q+3]);
        }
    }

    float* O = out + (size_t)b * CC * HWSZ + p;
    #pragma unroll
    for (int c = 0; c < 64; c++) O[(size_t)c * HWSZ] = acc[c];
}

extern "C" void kernel_launch(void* const* d_in, const int* in_sizes, int n_in,
                              void* d_out, int out_size) {
    const float* x  = (const float*)d_in[0];
    const float* gw = (const float*)d_in[1];
    const float* gb = (const float*)d_in[2];
    const float* w1 = (const float*)d_in[3];
    const float* b1 = (const float*)d_in[4];
    const float* w2 = (const float*)d_in[5];
    const float* b2 = (const float*)d_in[6];
    float* out = (float*)d_out;

    k_init<<<1, 32>>>();
    k_down<<<(BB*CC*HD*WD + 255) / 256, 256>>>(x);
    k_df<<<dim3(HWSZ/256, BB), 256>>>(x);
    k_gnstats<<<BB*CC, 256>>>(x);
    k_gnfin<<<1, 256>>>(gw, gb);
    k_main<<<dim3(HWSZ/256, BB), 256>>>(x);

    size_t smem = (size_t)(8192 + 8192 + 128 + 64) * sizeof(float);
    cudaFuncSetAttribute(k_ffn, cudaFuncAttributeMaxDynamicSharedMemorySize, (int)smem);
    k_ffn<<<(BB*HWSZ) / 128, 128, smem>>>(w1, b1, w2, b2, out);
}

// round 3
// speedup vs baseline: 1.0004x; 1.0004x over previous
#include <cuda_runtime.h>

#define BB 4
#define CC 64
#define HH 192
#define WWI 192
#define HWSZ (HH*WWI)
#define HD 96
#define WD 96

// ---- scratch (static device globals; no runtime allocation) ----
__device__ float g_down[BB*CC*HD*WD];          // 9.4 MB
__device__ float g_df[BB*HWSZ];
__device__ float g_nsq[BB*HWSZ];
__device__ unsigned g_dfmin[BB];
__device__ unsigned g_dfmax[BB];
__device__ float g_sum[BB*CC];
__device__ float g_ssq[BB*CC];
__device__ float g_A[BB*CC];
__device__ float g_Bc[BB*CC];

typedef unsigned long long ull;

__device__ __forceinline__ ull pack2(float lo, float hi) {
    ull r; asm("mov.b64 %0, {%1, %2};" : "=l"(r) : "f"(lo), "f"(hi)); return r;
}
__device__ __forceinline__ void unpack2(ull v, float& lo, float& hi) {
    asm("mov.b64 {%0, %1}, %2;" : "=f"(lo), "=f"(hi) : "l"(v));
}
__device__ __forceinline__ ull fma2(ull a, ull b, ull c) {
    ull d; asm("fma.rn.f32x2 %0, %1, %2, %3;" : "=l"(d) : "l"(a), "l"(b), "l"(c)); return d;
}
__device__ __forceinline__ ull add2(ull a, ull b) {
    ull d; asm("add.rn.f32x2 %0, %1, %2;" : "=l"(d) : "l"(a), "l"(b)); return d;
}

__global__ void k_init() {
    int t = blockIdx.x * 256 + threadIdx.x;
    if (t < BB) { g_dfmin[t] = 0x7f800000u; g_dfmax[t] = 0u; }
    if (t < BB*CC) { g_sum[t] = 0.f; g_ssq[t] = 0.f; }
}

// 0.5x bilinear == 2x2 average pooling; also accumulates GroupNorm sum/sumsq
// (every x element is read exactly once by this kernel).
// grid = BB*CC*2 blocks; each block does 48 down-rows of one (b,c) plane.
__global__ void k_down(const float* __restrict__ x) {
    int blk  = blockIdx.x;
    int bc   = blk >> 1;
    int half = blk & 1;
    const float* xp = x + (size_t)bc * HWSZ;
    float* dp = g_down + (size_t)bc * (HD*WD);

    float s = 0.f, q = 0.f;
    // 48 rows * 48 output-pairs = 2304 work items, 256 threads -> 9 iters
    for (int idx = threadIdx.x; idx < 48*48; idx += 256) {
        int jp = idx % 48;            // output pair index (outputs 2jp, 2jp+1)
        int r  = idx / 48;
        int ii = half * 48 + r;       // down row
        const float4 v0 = *(const float4*)(xp + (2*ii)   * WWI + 4*jp);
        const float4 v1 = *(const float4*)(xp + (2*ii+1) * WWI + 4*jp);
        // resize H first then W (exact 0.5 weights)
        float o0 = 0.5f*(0.5f*v0.x + 0.5f*v1.x) + 0.5f*(0.5f*v0.y + 0.5f*v1.y);
        float o1 = 0.5f*(0.5f*v0.z + 0.5f*v1.z) + 0.5f*(0.5f*v0.w + 0.5f*v1.w);
        dp[ii*WD + 2*jp]   = o0;
        dp[ii*WD + 2*jp+1] = o1;
        s += ((v0.x+v0.y)+(v0.z+v0.w)) + ((v1.x+v1.y)+(v1.z+v1.w));
        q += ((v0.x*v0.x+v0.y*v0.y)+(v0.z*v0.z+v0.w*v0.w))
           + ((v1.x*v1.x+v1.y*v1.y)+(v1.z*v1.z+v1.w*v1.w));
    }
    __shared__ float ss[256], sq[256];
    ss[threadIdx.x] = s; sq[threadIdx.x] = q;
    __syncthreads();
    for (int st = 128; st > 0; st >>= 1) {
        if (threadIdx.x < st) {
            ss[threadIdx.x] += ss[threadIdx.x+st];
            sq[threadIdx.x] += sq[threadIdx.x+st];
        }
        __syncthreads();
    }
    if (threadIdx.x == 0) {
        atomicAdd(&g_sum[bc], ss[0]);
        atomicAdd(&g_ssq[bc], sq[0]);
    }
}

// df map (sum_c |x - up(down(x))|), per-pixel normsq over C, per-batch min/max
__global__ void k_df(const float* __restrict__ x) {
    int p = blockIdx.x * 256 + threadIdx.x;   // 0..HWSZ-1 (exact)
    int b = blockIdx.y;
    int h = p / WWI, w = p % WWI;

    float sh = fminf(fmaxf((h + 0.5f) * 0.5f - 0.5f, 0.f), (float)(HD-1));
    float sw = fminf(fmaxf((w + 0.5f) * 0.5f - 0.5f, 0.f), (float)(WD-1));
    int hl = (int)sh; int hh2 = min(hl+1, HD-1); float wh = sh - (float)hl;
    int wl = (int)sw; int wh2 = min(wl+1, WD-1); float ww = sw - (float)wl;
    int i00 = hl*WD+wl, i10 = hh2*WD+wl, i01 = hl*WD+wh2, i11 = hh2*WD+wh2;

    const float* xb = x + (size_t)b * CC * HWSZ + p;
    const float* db = g_down + (size_t)b * CC * HD * WD;

    float df = 0.f, nsq = 0.f;
    #pragma unroll 8
    for (int c = 0; c < CC; c++) {
        float xv = xb[(size_t)c * HWSZ];
        const float* dc = db + c * HD * WD;
        float u0  = dc[i00]*(1.f-wh) + dc[i10]*wh;   // H interp
        float u1  = dc[i01]*(1.f-wh) + dc[i11]*wh;
        float xdu = u0*(1.f-ww) + u1*ww;             // then W interp
        df  += fabsf(xv - xdu);
        nsq += xv * xv;
    }
    g_df[b*HWSZ+p]  = df;
    g_nsq[b*HWSZ+p] = nsq;

    __shared__ float smn[256], smx[256];
    int tid = threadIdx.x;
    smn[tid] = df; smx[tid] = df;
    __syncthreads();
    for (int s = 128; s > 0; s >>= 1) {
        if (tid < s) {
            smn[tid] = fminf(smn[tid], smn[tid+s]);
            smx[tid] = fmaxf(smx[tid], smx[tid+s]);
        }
        __syncthreads();
    }
    if (tid == 0) {
        atomicMin(&g_dfmin[b], __float_as_uint(smn[0]));   // df >= 0: uint order == float order
        atomicMax(&g_dfmax[b], __float_as_uint(smx[0]));
    }
}

// fold GN(32 groups of 2 channels) into per-(b,c) affine A*x + B
__global__ void k_gnfin(const float* __restrict__ gw, const float* __restrict__ gb) {
    int t = threadIdx.x;              // 256 = BB*CC
    int c = t % CC;
    int g = c >> 1;
    int base = (t / CC) * CC + 2 * g;
    float n   = 2.f * (float)HWSZ;
    float mu  = (g_sum[base] + g_sum[base+1]) / n;
    float var = (g_ssq[base] + g_ssq[base+1]) / n - mu*mu;
    float inv = rsqrtf(var + 1e-5f);
    float A = gw[c] * inv;
    g_A[t]  = A;
    g_Bc[t] = gb[c] - mu * A;
}

// Fused: detail gating + cosine top-k aggregation + GN add -> enhanced (regs)
//        -> FFN with packed f32x2 FMAs -> out. No g_enh round-trip.
// smem layout (floats): sW1[8192] | sW2t[8192] | sb1[128] | sb2[64] | sA[64] | sB[64]
__global__ void __launch_bounds__(128) k_mainffn(
    const float* __restrict__ x,
    const float* __restrict__ w1, const float* __restrict__ b1,
    const float* __restrict__ w2, const float* __restrict__ b2,
    float* __restrict__ out)
{
    extern __shared__ float sm[];
    float* sW1  = sm;
    float* sW2t = sm + 8192;
    float* sb1  = sm + 16384;
    float* sb2  = sm + 16512;
    float* sA   = sm + 16576;
    float* sB   = sm + 16640;
    int tid = threadIdx.x;

    int n = blockIdx.x * 128 + tid;     // 0..BB*HWSZ-1 (exact); b constant per block
    int b = n / HWSZ;
    int p = n - b * HWSZ;

    for (int i = tid; i < 8192; i += 128) sW1[i] = w1[i];
    for (int i = tid; i < 8192; i += 128) {
        int o = i >> 6, c = i & 63;
        sW2t[i] = w2[c * 128 + o];
    }
    sb1[tid] = b1[tid];
    if (tid < 64) {
        sb2[tid] = b2[tid];
        sA[tid]  = g_A [b*CC + tid];
        sB[tid]  = g_Bc[b*CC + tid];
    }
    __syncthreads();

    // ---------------- phase A: enhanced[c] in registers ----------------
    int h = p / WWI, w = p % WWI;
    const float* xb = x + (size_t)b * CC * HWSZ + p;

    float dmin = __uint_as_float(g_dfmin[b]);
    float dmax = __uint_as_float(g_dfmax[b]);
    float df   = g_df[b*HWSZ + p];
    float t0   = (df - dmin) / ((dmax - dmin) + 1e-8f);
    float dfp  = t0 * t0;

    float e[64];

    if (!(dfp > 0.3f)) {   // not processed: enhanced = x + (A*x+B)
        #pragma unroll
        for (int c = 0; c < CC; c++) {
            float xv = xb[(size_t)c * HWSZ];
            e[c] = xv + (sA[c]*xv + sB[c]);
        }
    } else {
        int kk = min(1 + (int)rintf(dfp * 15.f), 9);

        bool val[9];
        int  doff[9];
        #pragma unroll
        for (int j = 0; j < 9; j++) {
            int dy = j/3 - 1, dx = j - 3*(j/3) - 1;
            val[j]  = ((unsigned)(h+dy) < HH) && ((unsigned)(w+dx) < WWI);
            doff[j] = dy * WWI + dx;
        }

        float dot[9];
        #pragma unroll
        for (int j = 0; j < 9; j++) dot[j] = 0.f;

        #pragma unroll 4
        for (int c = 0; c < CC; c++) {
            const float* rc = xb + (size_t)c * HWSZ;
            float xv = rc[0];
            #pragma unroll
            for (int j = 0; j < 9; j++)
                if (val[j]) dot[j] = fmaf(xv, rc[doff[j]], dot[j]);
        }

        float ncen = fmaxf(sqrtf(g_nsq[b*HWSZ + p]), 1e-12f);
        float sim[9];
        #pragma unroll
        for (int j = 0; j < 9; j++) {
            if (val[j]) {
                float nn = fmaxf(sqrtf(g_nsq[b*HWSZ + p + doff[j]]), 1e-12f);
                sim[j] = dot[j] / (ncen * nn);
            } else {
                sim[j] = 0.f;   // zero-padded patch -> sim = 0
            }
        }

        // stable top-k via rank (== stable argsort of -sim), all in registers
        float wt[9];
        float wsum = 0.f;
        #pragma unroll
        for (int j = 0; j < 9; j++) {
            int rank = 0;
            #pragma unroll
            for (int l = 0; l < 9; l++) {
                if (l != j) {
                    bool beats = (sim[l] > sim[j]) || (sim[l] == sim[j] && l < j);
                    rank += beats ? 1 : 0;
                }
            }
            float wv = (rank < kk) ? expf(sim[j]) : 0.f;
            wt[j] = wv;
            wsum += wv;
        }
        float invw = 1.f / fmaxf(wsum, 1e-12f);
        #pragma unroll
        for (int j = 0; j < 9; j++) wt[j] *= invw;

        #pragma unroll 4
        for (int c = 0; c < CC; c++) {
            const float* rc = xb + (size_t)c * HWSZ;
            float acc = 0.f;
            #pragma unroll
            for (int j = 0; j < 9; j++)
                if (val[j]) acc = fmaf(wt[j], rc[doff[j]], acc);
            float xv = rc[0];
            e[c] = acc + (sA[c]*xv + sB[c]);
        }
    }

    // ---------------- phase B: FFN with f32x2 channel-pair packing ----------------
    ull E2[32], acc2[32];
    #pragma unroll
    for (int q2 = 0; q2 < 32; q2++) {
        E2[q2]   = pack2(e[2*q2], e[2*q2+1]);
        acc2[q2] = add2(E2[q2], pack2(sb2[2*q2], sb2[2*q2+1]));   // enhanced + b2
    }

    #pragma unroll 2
    for (int o = 0; o < 128; o++) {
        const ulonglong2* wr = (const ulonglong2*)(sW1 + o * 64);  // 16 x (two f32x2)
        ull h2a = pack2(0.f, 0.f), h2b = pack2(0.f, 0.f);
        #pragma unroll
        for (int q2 = 0; q2 < 16; q2++) {
            ulonglong2 v = wr[q2];
            h2a = fma2(v.x, E2[2*q2],   h2a);
            h2b = fma2(v.y, E2[2*q2+1], h2b);
        }
        float a0, a1, b0, b1v;
        unpack2(h2a, a0, a1);
        unpack2(h2b, b0, b1v);
        float hh = fmaxf((a0 + a1) + (b0 + b1v) + sb1[o], 0.f);
        ull hh2 = pack2(hh, hh);

        const ulonglong2* wc = (const ulonglong2*)(sW2t + o * 64);
        #pragma unroll
        for (int q2 = 0; q2 < 16; q2++) {
            ulonglong2 v = wc[q2];
            acc2[2*q2]   = fma2(v.x, hh2, acc2[2*q2]);
            acc2[2*q2+1] = fma2(v.y, hh2, acc2[2*q2+1]);
        }
    }

    float* O = out + (size_t)b * CC * HWSZ + p;
    #pragma unroll
    for (int q2 = 0; q2 < 32; q2++) {
        float lo, hi;
        unpack2(acc2[q2], lo, hi);
        O[(size_t)(2*q2)   * HWSZ] = lo;
        O[(size_t)(2*q2+1) * HWSZ] = hi;
    }
}

extern "C" void kernel_launch(void* const* d_in, const int* in_sizes, int n_in,
                              void* d_out, int out_size) {
    const float* x  = (const float*)d_in[0];
    const float* gw = (const float*)d_in[1];
    const float* gb = (const float*)d_in[2];
    const float* w1 = (const float*)d_in[3];
    const float* b1 = (const float*)d_in[4];
    const float* w2 = (const float*)d_in[5];
    const float* b2 = (const float*)d_in[6];
    float* out = (float*)d_out;

    k_init<<<1, 256>>>();
    k_down<<<BB*CC*2, 256>>>(x);
    k_df<<<dim3(HWSZ/256, BB), 256>>>(x);
    k_gnfin<<<1, 256>>>(gw, gb);

    size_t smem = (size_t)(8192 + 8192 + 128 + 64 + 64 + 64) * sizeof(float);
    cudaFuncSetAttribute(k_mainffn, cudaFuncAttributeMaxDynamicSharedMemorySize, (int)smem);
    k_mainffn<<<(BB*HWSZ) / 128, 128, smem>>>(x, w1, b1, w2, b2, out);
}

// round 4
// speedup vs baseline: 1.0815x; 1.0810x over previous
#include <cuda_runtime.h>

#define BB 4
#define CC 64
#define HH 192
#define WWI 192
#define HWSZ (HH*WWI)
#define HD 96
#define WD 96

// ---- scratch (static device globals; no runtime allocation) ----
__device__ float g_down[BB*CC*HD*WD];          // 9.4 MB
__device__ float g_df[BB*HWSZ];
__device__ float g_nsq[BB*HWSZ];
__device__ unsigned g_dfmin[BB];
__device__ unsigned g_dfmax[BB];
__device__ float g_sum[BB*CC];
__device__ float g_ssq[BB*CC];
__device__ float g_A[BB*CC];
__device__ float g_Bc[BB*CC];

// W1 + b1 live in constant memory: loads go through the constant port,
// off the smem crossbar (which is the measured bottleneck).
__constant__ float cW1[128*64];   // 32 KB
__constant__ float cB1[128];

typedef unsigned long long ull;

__device__ __forceinline__ ull pack2(float lo, float hi) {
    ull r; asm("mov.b64 %0, {%1, %2};" : "=l"(r) : "f"(lo), "f"(hi)); return r;
}
__device__ __forceinline__ void unpack2(ull v, float& lo, float& hi) {
    asm("mov.b64 {%0, %1}, %2;" : "=f"(lo), "=f"(hi) : "l"(v));
}
__device__ __forceinline__ ull fma2(ull a, ull b, ull c) {
    ull d; asm("fma.rn.f32x2 %0, %1, %2, %3;" : "=l"(d) : "l"(a), "l"(b), "l"(c)); return d;
}
__device__ __forceinline__ ull add2(ull a, ull b) {
    ull d; asm("add.rn.f32x2 %0, %1, %2;" : "=l"(d) : "l"(a), "l"(b)); return d;
}

__global__ void k_init() {
    int t = blockIdx.x * 256 + threadIdx.x;
    if (t < BB) { g_dfmin[t] = 0x7f800000u; g_dfmax[t] = 0u; }
    if (t < BB*CC) { g_sum[t] = 0.f; g_ssq[t] = 0.f; }
}

// 0.5x bilinear == 2x2 average pooling; also accumulates GroupNorm sum/sumsq.
__global__ void k_down(const float* __restrict__ x) {
    int blk  = blockIdx.x;
    int bc   = blk >> 1;
    int half = blk & 1;
    const float* xp = x + (size_t)bc * HWSZ;
    float* dp = g_down + (size_t)bc * (HD*WD);

    float s = 0.f, q = 0.f;
    for (int idx = threadIdx.x; idx < 48*48; idx += 256) {
        int jp = idx % 48;
        int r  = idx / 48;
        int ii = half * 48 + r;
        const float4 v0 = *(const float4*)(xp + (2*ii)   * WWI + 4*jp);
        const float4 v1 = *(const float4*)(xp + (2*ii+1) * WWI + 4*jp);
        float o0 = 0.5f*(0.5f*v0.x + 0.5f*v1.x) + 0.5f*(0.5f*v0.y + 0.5f*v1.y);
        float o1 = 0.5f*(0.5f*v0.z + 0.5f*v1.z) + 0.5f*(0.5f*v0.w + 0.5f*v1.w);
        dp[ii*WD + 2*jp]   = o0;
        dp[ii*WD + 2*jp+1] = o1;
        s += ((v0.x+v0.y)+(v0.z+v0.w)) + ((v1.x+v1.y)+(v1.z+v1.w));
        q += ((v0.x*v0.x+v0.y*v0.y)+(v0.z*v0.z+v0.w*v0.w))
           + ((v1.x*v1.x+v1.y*v1.y)+(v1.z*v1.z+v1.w*v1.w));
    }
    __shared__ float ss[256], sq[256];
    ss[threadIdx.x] = s; sq[threadIdx.x] = q;
    __syncthreads();
    for (int st = 128; st > 0; st >>= 1) {
        if (threadIdx.x < st) {
            ss[threadIdx.x] += ss[threadIdx.x+st];
            sq[threadIdx.x] += sq[threadIdx.x+st];
        }
        __syncthreads();
    }
    if (threadIdx.x == 0) {
        atomicAdd(&g_sum[bc], ss[0]);
        atomicAdd(&g_ssq[bc], sq[0]);
    }
}

// df map (sum_c |x - up(down(x))|), per-pixel normsq over C, per-batch min/max
__global__ void k_df(const float* __restrict__ x) {
    int p = blockIdx.x * 256 + threadIdx.x;
    int b = blockIdx.y;
    int h = p / WWI, w = p % WWI;

    float sh = fminf(fmaxf((h + 0.5f) * 0.5f - 0.5f, 0.f), (float)(HD-1));
    float sw = fminf(fmaxf((w + 0.5f) * 0.5f - 0.5f, 0.f), (float)(WD-1));
    int hl = (int)sh; int hh2 = min(hl+1, HD-1); float wh = sh - (float)hl;
    int wl = (int)sw; int wh2 = min(wl+1, WD-1); float ww = sw - (float)wl;
    int i00 = hl*WD+wl, i10 = hh2*WD+wl, i01 = hl*WD+wh2, i11 = hh2*WD+wh2;

    const float* xb = x + (size_t)b * CC * HWSZ + p;
    const float* db = g_down + (size_t)b * CC * HD * WD;

    float df = 0.f, nsq = 0.f;
    #pragma unroll 8
    for (int c = 0; c < CC; c++) {
        float xv = xb[(size_t)c * HWSZ];
        const float* dc = db + c * HD * WD;
        float u0  = dc[i00]*(1.f-wh) + dc[i10]*wh;
        float u1  = dc[i01]*(1.f-wh) + dc[i11]*wh;
        float xdu = u0*(1.f-ww) + u1*ww;
        df  += fabsf(xv - xdu);
        nsq += xv * xv;
    }
    g_df[b*HWSZ+p]  = df;
    g_nsq[b*HWSZ+p] = nsq;

    __shared__ float smn[256], smx[256];
    int tid = threadIdx.x;
    smn[tid] = df; smx[tid] = df;
    __syncthreads();
    for (int s = 128; s > 0; s >>= 1) {
        if (tid < s) {
            smn[tid] = fminf(smn[tid], smn[tid+s]);
            smx[tid] = fmaxf(smx[tid], smx[tid+s]);
        }
        __syncthreads();
    }
    if (tid == 0) {
        atomicMin(&g_dfmin[b], __float_as_uint(smn[0]));
        atomicMax(&g_dfmax[b], __float_as_uint(smx[0]));
    }
}

// fold GN(32 groups of 2 channels) into per-(b,c) affine A*x + B
__global__ void k_gnfin(const float* __restrict__ gw, const float* __restrict__ gb) {
    int t = threadIdx.x;              // 256 = BB*CC
    int c = t % CC;
    int g = c >> 1;
    int base = (t / CC) * CC + 2 * g;
    float n   = 2.f * (float)HWSZ;
    float mu  = (g_sum[base] + g_sum[base+1]) / n;
    float var = (g_ssq[base] + g_ssq[base+1]) / n - mu*mu;
    float inv = rsqrtf(var + 1e-5f);
    float A = gw[c] * inv;
    g_A[t]  = A;
    g_Bc[t] = gb[c] - mu * A;
}

// Fused: detail gating + cosine top-k + GN add -> enhanced (regs) -> FFN -> out.
// GEMM1 weights from __constant__ (constant port), GEMM2 weights from smem.
// smem layout (floats): sW2t[8192] | sb2[64] | sA[64] | sB[64]
__global__ void __launch_bounds__(128) k_mainffn(
    const float* __restrict__ x,
    const float* __restrict__ w2, const float* __restrict__ b2,
    float* __restrict__ out)
{
    extern __shared__ float sm[];
    float* sW2t = sm;
    float* sb2  = sm + 8192;
    float* sA   = sm + 8256;
    float* sB   = sm + 8320;
    int tid = threadIdx.x;

    int n = blockIdx.x * 128 + tid;     // b constant per block (HWSZ % 128 == 0)
    int b = n / HWSZ;
    int p = n - b * HWSZ;

    for (int i = tid; i < 8192; i += 128) {
        int o = i >> 6, c = i & 63;
        sW2t[i] = w2[c * 128 + o];
    }
    if (tid < 64) {
        sb2[tid] = b2[tid];
        sA[tid]  = g_A [b*CC + tid];
        sB[tid]  = g_Bc[b*CC + tid];
    }
    __syncthreads();

    // ---------------- phase A: enhanced[c] in registers ----------------
    int h = p / WWI, w = p % WWI;
    const float* xb = x + (size_t)b * CC * HWSZ + p;

    float dmin = __uint_as_float(g_dfmin[b]);
    float dmax = __uint_as_float(g_dfmax[b]);
    float df   = g_df[b*HWSZ + p];
    float t0   = (df - dmin) / ((dmax - dmin) + 1e-8f);
    float dfp  = t0 * t0;

    float e[64];

    if (!(dfp > 0.3f)) {   // not processed: enhanced = x + (A*x+B)
        #pragma unroll
        for (int c = 0; c < CC; c++) {
            float xv = xb[(size_t)c * HWSZ];
            e[c] = xv + (sA[c]*xv + sB[c]);
        }
    } else {
        int kk = min(1 + (int)rintf(dfp * 15.f), 9);

        bool val[9];
        int  doff[9];
        #pragma unroll
        for (int j = 0; j < 9; j++) {
            int dy = j/3 - 1, dx = j - 3*(j/3) - 1;
            val[j]  = ((unsigned)(h+dy) < HH) && ((unsigned)(w+dx) < WWI);
            doff[j] = dy * WWI + dx;
        }

        float dot[9];
        #pragma unroll
        for (int j = 0; j < 9; j++) dot[j] = 0.f;

        #pragma unroll 4
        for (int c = 0; c < CC; c++) {
            const float* rc = xb + (size_t)c * HWSZ;
            float xv = rc[0];
            #pragma unroll
            for (int j = 0; j < 9; j++)
                if (val[j]) dot[j] = fmaf(xv, rc[doff[j]], dot[j]);
        }

        float ncen = fmaxf(sqrtf(g_nsq[b*HWSZ + p]), 1e-12f);
        float sim[9];
        #pragma unroll
        for (int j = 0; j < 9; j++) {
            if (val[j]) {
                float nn = fmaxf(sqrtf(g_nsq[b*HWSZ + p + doff[j]]), 1e-12f);
                sim[j] = dot[j] / (ncen * nn);
            } else {
                sim[j] = 0.f;
            }
        }

        // stable top-k via rank (== stable argsort of -sim), in registers
        float wt[9];
        float wsum = 0.f;
        #pragma unroll
        for (int j = 0; j < 9; j++) {
            int rank = 0;
            #pragma unroll
            for (int l = 0; l < 9; l++) {
                if (l != j) {
                    bool beats = (sim[l] > sim[j]) || (sim[l] == sim[j] && l < j);
                    rank += beats ? 1 : 0;
                }
            }
            float wv = (rank < kk) ? expf(sim[j]) : 0.f;
            wt[j] = wv;
            wsum += wv;
        }
        float invw = 1.f / fmaxf(wsum, 1e-12f);
        #pragma unroll
        for (int j = 0; j < 9; j++) wt[j] *= invw;

        #pragma unroll 4
        for (int c = 0; c < CC; c++) {
            const float* rc = xb + (size_t)c * HWSZ;
            float acc = 0.f;
            #pragma unroll
            for (int j = 0; j < 9; j++)
                if (val[j]) acc = fmaf(wt[j], rc[doff[j]], acc);
            float xv = rc[0];
            e[c] = acc + (sA[c]*xv + sB[c]);
        }
    }

    // ---------------- phase B: FFN (W1 const / W2 smem, f32x2 FMAs) ----------------
    ull E2[32], acc2[32];
    #pragma unroll
    for (int q2 = 0; q2 < 32; q2++) {
        E2[q2]   = pack2(e[2*q2], e[2*q2+1]);
        acc2[q2] = add2(E2[q2], pack2(sb2[2*q2], sb2[2*q2+1]));
    }

    #pragma unroll 2
    for (int o = 0; o < 128; o++) {
        const ulonglong2* wr = (const ulonglong2*)(cW1 + o * 64);  // constant port
        ull h2a = pack2(0.f, 0.f), h2b = pack2(0.f, 0.f);
        #pragma unroll
        for (int q2 = 0; q2 < 16; q2++) {
            ulonglong2 v = wr[q2];
            h2a = fma2(v.x, E2[2*q2],   h2a);
            h2b = fma2(v.y, E2[2*q2+1], h2b);
        }
        float a0, a1, b0, b1v;
        unpack2(h2a, a0, a1);
        unpack2(h2b, b0, b1v);
        float hh = fmaxf((a0 + a1) + (b0 + b1v) + cB1[o], 0.f);
        ull hh2 = pack2(hh, hh);

        const ulonglong2* wc = (const ulonglong2*)(sW2t + o * 64);  // smem crossbar
        #pragma unroll
        for (int q2 = 0; q2 < 16; q2++) {
            ulonglong2 v = wc[q2];
            acc2[2*q2]   = fma2(v.x, hh2, acc2[2*q2]);
            acc2[2*q2+1] = fma2(v.y, hh2, acc2[2*q2+1]);
        }
    }

    float* O = out + (size_t)b * CC * HWSZ + p;
    #pragma unroll
    for (int q2 = 0; q2 < 32; q2++) {
        float lo, hi;
        unpack2(acc2[q2], lo, hi);
        O[(size_t)(2*q2)   * HWSZ] = lo;
        O[(size_t)(2*q2+1) * HWSZ] = hi;
    }
}

extern "C" void kernel_launch(void* const* d_in, const int* in_sizes, int n_in,
                              void* d_out, int out_size) {
    const float* x  = (const float*)d_in[0];
    const float* gw = (const float*)d_in[1];
    const float* gb = (const float*)d_in[2];
    const float* w1 = (const float*)d_in[3];
    const float* b1 = (const float*)d_in[4];
    const float* w2 = (const float*)d_in[5];
    const float* b2 = (const float*)d_in[6];
    float* out = (float*)d_out;

    // device-to-device async copies into constant bank (graph-capturable)
    cudaMemcpyToSymbolAsync(cW1, w1, 128*64*sizeof(float), 0, cudaMemcpyDeviceToDevice);
    cudaMemcpyToSymbolAsync(cB1, b1, 128*sizeof(float),    0, cudaMemcpyDeviceToDevice);

    k_init<<<1, 256>>>();
    k_down<<<BB*CC*2, 256>>>(x);
    k_df<<<dim3(HWSZ/256, BB), 256>>>(x);
    k_gnfin<<<1, 256>>>(gw, gb);

    size_t smem = (size_t)(8192 + 64 + 64 + 64) * sizeof(float);
    cudaFuncSetAttribute(k_mainffn, cudaFuncAttributeMaxDynamicSharedMemorySize, (int)smem);
    k_mainffn<<<(BB*HWSZ) / 128, 128, smem>>>(x, w2, b2, out);
}